// round 10
// baseline (speedup 1.0000x reference)
#include <cuda_runtime.h>
#include <stdint.h>

// x [n,c,h,w] fp32; per (n,c) row of hw=4096 keep top-k by |x|.
// out = x (kept) or x*(1-tau) (dropped).
// One CTA (512 thr) per row, data register-resident (key = bits<<1).
// Select: 11-bit histogram (2048 bins) -> gather crossing class (<=256) ->
// 8-bit histogram over the list -> gather subclass (<=64) -> 13-bit
// single-warp ballot search. Exact cold fallback: counting binary search.

constexpr int HW      = 4096;
constexpr int THREADS = 512;
constexpr int EPT     = HW / THREADS;    // 8
constexpr int NW      = THREADS / 32;    // 16
constexpr int NBIN    = 2048;
constexpr int BPT     = NBIN / THREADS;  // 4 bins per thread
constexpr int CAP1    = 256;
constexpr int CAP2    = 64;
constexpr unsigned FULL = 0xFFFFFFFFu;

__global__ __launch_bounds__(THREADS)
void topk_blend_kernel(const float* __restrict__ x,
                       const float* __restrict__ tau_p,
                       const int*   __restrict__ k_p,
                       float*       __restrict__ out)
{
    __shared__ uint32_t hist[NBIN];
    __shared__ uint32_t wtot[NW];
    __shared__ uint32_t wtie[NW];
    __shared__ uint32_t list1[CAP1];     // 21-bit remainders
    __shared__ uint32_t list2[CAP2];     // 13-bit remainders
    __shared__ uint32_t s_bin, s_krem, s_n1, s_n2, s_T, s_need, s_mode, s_cnt;

    const int tid  = threadIdx.x;
    const int wid  = tid >> 5;
    const int lane = tid & 31;
    const size_t base = (size_t)blockIdx.x * HW;

    // Blocked vectorized load: thread t owns elements [t*8, t*8+8)
    uint32_t b[EPT];
    const uint4* __restrict__ xin = reinterpret_cast<const uint4*>(x + base);
    {
        uint4 v0 = xin[tid*2+0], v1 = xin[tid*2+1];
        b[0]=v0.x; b[1]=v0.y; b[2]=v0.z; b[3]=v0.w;
        b[4]=v1.x; b[5]=v1.y; b[6]=v1.z; b[7]=v1.w;
    }

    const float tau = __ldg(tau_p);
    const int   K   = __ldg(k_p);

    // zero hist: 2048 words / 512 thr = 1 x uint4 per thread
    reinterpret_cast<uint4*>(hist)[tid] = make_uint4(0,0,0,0);
    __syncthreads();                                            // B1

    uint32_t T = 0, need = 0;
    int  t_excl = 0;
    bool geq = false;
    const bool sel = (K > 0 && K < HW);

    if (sel) {
        // ========== 11-bit histogram (key bits 31..21) ==========
        #pragma unroll
        for (int j = 0; j < EPT; j++)
            atomicAdd(&hist[(b[j] >> 20) & 0x7FFu], 1u);
        __syncthreads();                                        // B2

        // ========== scan over 2048 bins (4 per thread) ==========
        {
            const int b0 = tid * BPT;
            uint4 h = reinterpret_cast<uint4*>(hist)[tid];
            reinterpret_cast<uint4*>(hist)[tid] = make_uint4(0,0,0,0);
            uint32_t c[4] = {h.x, h.y, h.z, h.w};
            uint32_t suf[4];
            suf[3] = c[3];
            #pragma unroll
            for (int i = 2; i >= 0; i--) suf[i] = c[i] + suf[i+1];
            const uint32_t tot = suf[0];

            uint32_t s = tot;                      // inclusive suffix over lanes
            #pragma unroll
            for (int off = 1; off < 32; off <<= 1) {
                uint32_t v = __shfl_down_sync(FULL, s, off);
                if (lane + off < 32) s += v;
            }
            const uint32_t lane_hi = s - tot;      // lanes > lane
            if (lane == 0) wtot[wid] = s;          // warp total
            __syncthreads();                                    // B3

            uint32_t warp_hi = 0;
            #pragma unroll
            for (int w = 0; w < NW; w++) if (w > wid) warp_hi += wtot[w];
            const uint32_t off = lane_hi + warp_hi;
            const uint32_t Ku = (uint32_t)K;
            #pragma unroll
            for (int i = 0; i < 4; i++) {
                uint32_t incl  = suf[i] + off;     // count of keys with bin >= b0+i
                uint32_t above = incl - c[i];
                if (above < Ku && Ku <= incl) {    // exactly one (thread,i)
                    s_bin  = (uint32_t)(b0 + i);
                    s_krem = Ku - above;
                }
            }
            if (tid == 0) s_n1 = 0;
        }
        __syncthreads();                                        // B4

        const uint32_t binsel = s_bin;
        const uint32_t krem1  = s_krem;

        // ========== gather crossing-class candidates ==========
        #pragma unroll
        for (int j = 0; j < EPT; j++) {
            uint32_t key = b[j] << 1;
            if ((key >> 21) == binsel) {
                uint32_t pos = atomicAdd(&s_n1, 1u);
                if (pos < CAP1) list1[pos] = key & 0x1FFFFFu;
            }
        }
        __syncthreads();                                        // B5
        const uint32_t n1 = s_n1;

        if (n1 <= CAP1) {
            // ===== 8-bit histogram over the list (bits 20..13) =====
            if (tid < (int)n1)
                atomicAdd(&hist[(list1[tid] >> 13) & 0xFFu], 1u);
            __syncthreads();                                    // B6

            // ===== scan 256 bins (threads 0..255) =====
            if (tid < 256) {
                uint32_t c2 = hist[tid];
                hist[tid] = 0;
                uint32_t s2 = c2;
                #pragma unroll
                for (int off = 1; off < 32; off <<= 1) {
                    uint32_t v = __shfl_down_sync(FULL, s2, off);
                    if (lane + off < 32) s2 += v;
                }
                if (lane == 0) wtot[wid] = s2;
                __syncthreads();                                // B7
                uint32_t hi2 = 0;
                #pragma unroll
                for (int w = 0; w < 8; w++) if (w > wid) hi2 += wtot[w];
                uint32_t incl2  = s2 + hi2;
                uint32_t above2 = incl2 - c2;
                if (above2 < krem1 && krem1 <= incl2) {
                    s_bin  = (uint32_t)tid;
                    s_krem = krem1 - above2;
                }
                if (tid == 0) s_n2 = 0;
            } else {
                __syncthreads();                                // B7 (uniform)
            }
            __syncthreads();                                    // B8

            const uint32_t bin2  = s_bin;
            const uint32_t krem2 = s_krem;

            // ===== gather subclass =====
            if (tid < (int)n1) {
                uint32_t v = list1[tid];
                if (((v >> 13) & 0xFFu) == bin2) {
                    uint32_t pos = atomicAdd(&s_n2, 1u);
                    if (pos < CAP2) list2[pos] = v & 0x1FFFu;
                }
            }
            __syncthreads();                                    // B9
            const uint32_t n2 = s_n2;

            if (n2 <= CAP2) {
                // ===== single-warp 13-bit ballot search =====
                if (wid == 0) {
                    uint32_t cand[2]; bool val[2];
                    #pragma unroll
                    for (int i = 0; i < 2; i++) {
                        int idx = lane + 32 * i;
                        val[i]  = idx < (int)n2;
                        cand[i] = val[i] ? list2[idx] : 0u;
                    }
                    auto cnt_ge = [&](uint32_t t) -> uint32_t {
                        uint32_t n = 0;
                        #pragma unroll
                        for (int i = 0; i < 2; i++)
                            n += (uint32_t)__popc(__ballot_sync(FULL, val[i] && cand[i] >= t));
                        return n;
                    };
                    uint32_t v = 0;
                    #pragma unroll
                    for (int bit = 12; bit >= 0; bit--) {
                        uint32_t t = v | (1u << bit);
                        if (cnt_ge(t) >= krem2) v = t;
                    }
                    uint32_t n_gt = cnt_ge(v + 1);
                    uint32_t n_eq = cnt_ge(v) - n_gt;
                    uint32_t nd   = krem2 - n_gt;           // >= 1
                    if (lane == 0) {
                        s_T    = (binsel << 21) | (bin2 << 13) | v;
                        s_need = nd;
                        s_mode = (nd == n_eq) ? 1u : 0u;
                    }
                }
            } else {
                if (tid == 0) s_mode = 2u;                   // fallback
            }
            __syncthreads();                                // B10
        } else {
            if (tid == 0) s_mode = 2u;
            __syncthreads();                                // B6' (uniform path)
            __syncthreads();                                // B7'
            __syncthreads();                                // B8'
            __syncthreads();                                // B9'
            __syncthreads();                                // B10'
        }

        const uint32_t mode = s_mode;
        if (mode != 2u) {
            T    = s_T;
            need = s_need;
            geq  = (mode == 1u);
        } else {
            // ===== exact cold fallback: counting binary search on full key =====
            uint32_t Tf = 0;
            const uint32_t Ku = (uint32_t)K;
            for (int bit = 30; bit >= 0; bit--) {
                if (tid == 0) s_cnt = 0;
                __syncthreads();
                uint32_t trial = Tf | (1u << bit);
                uint32_t cnt = 0;
                #pragma unroll
                for (int j = 0; j < EPT; j++) cnt += ((b[j] << 1) >= trial);
                #pragma unroll
                for (int off = 16; off >= 1; off >>= 1)
                    cnt += __shfl_down_sync(FULL, cnt, off);
                if (lane == 0) atomicAdd(&s_cnt, cnt);
                __syncthreads();
                if (s_cnt >= Ku) Tf = trial;
                __syncthreads();
            }
            uint32_t n_ge = 0, n_gt = 0;
            {
                if (tid == 0) s_cnt = 0;
                __syncthreads();
                uint32_t cnt = 0;
                #pragma unroll
                for (int j = 0; j < EPT; j++) cnt += ((b[j] << 1) >= Tf);
                #pragma unroll
                for (int off = 16; off >= 1; off >>= 1)
                    cnt += __shfl_down_sync(FULL, cnt, off);
                if (lane == 0) atomicAdd(&s_cnt, cnt);
                __syncthreads();
                n_ge = s_cnt;
                __syncthreads();
                if (tid == 0) s_cnt = 0;
                __syncthreads();
                cnt = 0;
                #pragma unroll
                for (int j = 0; j < EPT; j++) cnt += ((b[j] << 1) > Tf);
                #pragma unroll
                for (int off = 16; off >= 1; off >>= 1)
                    cnt += __shfl_down_sync(FULL, cnt, off);
                if (lane == 0) atomicAdd(&s_cnt, cnt);
                __syncthreads();
                n_gt = s_cnt;
            }
            T    = Tf;
            need = Ku - n_gt;
            geq  = (need == (n_ge - n_gt));
        }

        // ===== stable tie rank (only when threshold value duplicated) =====
        if (!geq) {
            int myeq = 0;
            #pragma unroll
            for (int j = 0; j < EPT; j++) myeq += ((b[j] << 1) == T);
            uint32_t e = (uint32_t)myeq;
            #pragma unroll
            for (int off = 1; off < 32; off <<= 1) {
                uint32_t v = __shfl_up_sync(FULL, e, off);
                if (lane >= off) e += v;
            }
            if (lane == 31) wtie[wid] = e;
            __syncthreads();
            uint32_t lo = 0;
            #pragma unroll
            for (int w = 0; w < NW; w++) if (w < wid) lo += wtie[w];
            t_excl = (int)(e - (uint32_t)myeq + lo);
        }
    }

    // ========== apply: out = kept ? x : x*(1-tau) ==========
    const float omt = 1.0f - tau;
    float4* __restrict__ yout = reinterpret_cast<float4*>(out + base);
    int rank = t_excl;
    const int needi = (int)need;
    #pragma unroll
    for (int i = 0; i < 2; i++) {
        float r[4];
        #pragma unroll
        for (int j = 0; j < 4; j++) {
            const int idx = i * 4 + j;
            uint32_t key = b[idx] << 1;
            bool keep;
            if (!sel)     keep = (K >= HW);
            else if (geq) keep = (key >= T);
            else {
                keep = (key > T) | ((key == T) & (rank < needi));
                rank += (key == T);
            }
            float xv = __uint_as_float(b[idx]);
            r[j] = keep ? xv : xv * omt;
        }
        yout[tid * 2 + i] = make_float4(r[0], r[1], r[2], r[3]);
    }
}

extern "C" void kernel_launch(void* const* d_in, const int* in_sizes, int n_in,
                              void* d_out, int out_size)
{
    const float* x   = (const float*)d_in[0];
    const float* tau = (const float*)d_in[1];
    const int*   k   = (const int*)d_in[2];
    float*       out = (float*)d_out;
    const int    rows = in_sizes[0] / HW;   // n*c = 8192

    topk_blend_kernel<<<rows, THREADS>>>(x, tau, k, out);
}